// round 1
// baseline (speedup 1.0000x reference)
#include <cuda_runtime.h>
#include <math.h>
#include <stdint.h>

#define NB 48
#define NC 768
#define NS 361
#define NT 64
#define SP 364   // padded S (multiple of 4)

#define TEMP1 4.0f
#define TEMP2 5.0f
#define TEMP3 10.0f
#define EPSV  1e-8f

// ----- device scratch (no allocations allowed) -----
__device__ float g_G[NB * NS * NS];   // 25 MB Gram matrices
__device__ float g_w1n[NB * NT];
__device__ float g_gn[NB];
__device__ float g_sn[NB];
__device__ float g_sc0[NB * NB];
__device__ float g_sims[NB * NB];     // similarities[img][cap]

__device__ __forceinline__ void fma4x4(float (&acc)[4][4], float4 a, float4 b) {
    acc[0][0] = fmaf(a.x, b.x, acc[0][0]); acc[0][1] = fmaf(a.x, b.y, acc[0][1]);
    acc[0][2] = fmaf(a.x, b.z, acc[0][2]); acc[0][3] = fmaf(a.x, b.w, acc[0][3]);
    acc[1][0] = fmaf(a.y, b.x, acc[1][0]); acc[1][1] = fmaf(a.y, b.y, acc[1][1]);
    acc[1][2] = fmaf(a.y, b.z, acc[1][2]); acc[1][3] = fmaf(a.y, b.w, acc[1][3]);
    acc[2][0] = fmaf(a.z, b.x, acc[2][0]); acc[2][1] = fmaf(a.z, b.y, acc[2][1]);
    acc[2][2] = fmaf(a.z, b.z, acc[2][2]); acc[2][3] = fmaf(a.z, b.w, acc[2][3]);
    acc[3][0] = fmaf(a.w, b.x, acc[3][0]); acc[3][1] = fmaf(a.w, b.y, acc[3][1]);
    acc[3][2] = fmaf(a.w, b.z, acc[3][2]); acc[3][3] = fmaf(a.w, b.w, acc[3][3]);
}

// ============================================================
// Gram: G_b = ctx_b^T ctx_b  (361x361, K=768), tiled 64x64
// grid (6,6,48), 256 threads
// ============================================================
__global__ __launch_bounds__(256) void gram_kernel(const float* __restrict__ ctx_all) {
    int b = blockIdx.z;
    int i0 = blockIdx.y * 64, j0 = blockIdx.x * 64;
    __shared__ float At[32 * 64];
    __shared__ float Bt[32 * 64];
    const float* ctx = ctx_all + (size_t)b * NC * NS;
    int tid = threadIdx.x;
    int ti = tid & 15, si = tid >> 4;
    float acc[4][4] = {};
    for (int kc = 0; kc < NC / 32; ++kc) {
        int k0 = kc * 32;
        __syncthreads();
        for (int i = tid; i < 32 * 64; i += 256) {
            int kk = i >> 6, ii = i & 63;
            int gi = i0 + ii, gj = j0 + ii;
            At[i] = (gi < NS) ? ctx[(size_t)(k0 + kk) * NS + gi] : 0.f;
            Bt[i] = (gj < NS) ? ctx[(size_t)(k0 + kk) * NS + gj] : 0.f;
        }
        __syncthreads();
#pragma unroll 8
        for (int k = 0; k < 32; ++k) {
            float4 av = *(const float4*)&At[k * 64 + si * 4];
            float4 bv = *(const float4*)&Bt[k * 64 + ti * 4];
            fma4x4(acc, av, bv);
        }
    }
    float* Gb = g_G + (size_t)b * NS * NS;
#pragma unroll
    for (int ii = 0; ii < 4; ++ii) {
        int gi = i0 + si * 4 + ii;
        if (gi < NS) {
#pragma unroll
            for (int jj = 0; jj < 4; ++jj) {
                int gj = j0 + ti * 4 + jj;
                if (gj < NS) Gb[(size_t)gi * NS + gj] = acc[ii][jj];
            }
        }
    }
}

// ============================================================
// Norms: w1[c][t] = ||words[c,:,t]||, plus global/sent feature norms
// grid 48, 64 threads
// ============================================================
__global__ void norms_kernel(const float* __restrict__ words,
                             const float* __restrict__ gfeat,
                             const float* __restrict__ sfeat) {
    int c = blockIdx.x;
    int tid = threadIdx.x;
    float s = 0.f;
    for (int d = 0; d < NC; ++d) {
        float v = words[((size_t)c * NC + d) * NT + tid];
        s = fmaf(v, v, s);
    }
    g_w1n[c * NT + tid] = sqrtf(s);

    float a = 0.f, bb = 0.f;
    for (int d = tid; d < NC; d += 64) {
        float v = gfeat[(size_t)c * NC + d];
        float w = sfeat[(size_t)c * NC + d];
        a = fmaf(v, v, a);
        bb = fmaf(w, w, bb);
    }
#pragma unroll
    for (int o = 16; o; o >>= 1) {
        a  += __shfl_xor_sync(0xffffffffu, a, o);
        bb += __shfl_xor_sync(0xffffffffu, bb, o);
    }
    __shared__ float r[4];
    int warp = tid >> 5, lane = tid & 31;
    if (lane == 0) { r[warp] = a; r[2 + warp] = bb; }
    __syncthreads();
    if (tid == 0) {
        g_gn[c] = sqrtf(r[0] + r[1]);
        g_sn[c] = sqrtf(r[2] + r[3]);
    }
}

// ============================================================
// Global scores0: grid 48 (row i), 256 threads
// ============================================================
__global__ void gscore_kernel(const float* __restrict__ gfeat,
                              const float* __restrict__ sfeat) {
    int i = blockIdx.x;
    int tid = threadIdx.x;
    int warp = tid >> 5, lane = tid & 31;
    for (int j = warp; j < NB; j += 8) {
        float acc = 0.f;
        for (int d = lane; d < NC; d += 32)
            acc = fmaf(gfeat[(size_t)i * NC + d], sfeat[(size_t)j * NC + d], acc);
#pragma unroll
        for (int o = 16; o; o >>= 1) acc += __shfl_xor_sync(0xffffffffu, acc, o);
        if (lane == 0) {
            float denom = fmaxf(g_gn[i] * g_sn[j], EPSV);
            g_sc0[i * NB + j] = TEMP3 * acc / denom;
        }
    }
}

// ============================================================
// Per-pair kernel: one CTA per (cap c, img b); 256 threads
// smem: scores[SP*64] (reused as Gsub) | a2buf[SP*64] | ctile[4096] | wtile[4096] | misc
// ============================================================
#define SMEM_FLOATS (SP * NT * 2 + 4096 * 2 + 64 * 3 + 256)
#define SMEM_BYTES  (SMEM_FLOATS * 4)

__global__ __launch_bounds__(256, 1) void pair_kernel(
    const float* __restrict__ local_f,   // [B,C,S]
    const float* __restrict__ words,     // [B,C,T]
    const int*   __restrict__ cap_lens,
    float*       __restrict__ att_out,   // d_out+1 (or ignored)
    int write_att) {
    extern __shared__ float smem[];
    float* scoresB = smem;                  // SP*64 (361 rows used; reused as Gsub)
    float* a2buf   = smem + SP * NT;        // SP*64
    float* ctile   = a2buf + SP * NT;       // 64*64
    float* wtile   = ctile + 4096;          // 64*64
    float* colinv  = wtile + 4096;          // 64
    float* w12s    = colinv + 64;           // 64
    float* w2sq    = w12s + 64;             // 64
    float* red     = w2sq + 64;             // 256

    int tid = threadIdx.x;
    int bidx = blockIdx.x;
    int b = bidx % NB;        // image
    int c = bidx / NB;        // caption
    const float* ctx = local_f + (size_t)b * NC * NS;
    const float* wrd = words + (size_t)c * NC * NT;

    int ti = tid & 15, si = tid >> 4;
    int t0 = ti * 4, s0l = si * 4;

    // ---------- Phase 1: scores[s][t] = sum_d ctx[d][s]*w[d][t] ----------
    for (int p = 0; p < 6; ++p) {
        int sbase = p * 64;
        float acc[4][4] = {};
        for (int kc = 0; kc < 12; ++kc) {
            int k0 = kc * 64;
            __syncthreads();
            for (int i = tid; i < 4096; i += 256) {
                int d = i >> 6, x = i & 63;
                int gs = sbase + x;
                ctile[i] = (gs < NS) ? ctx[(size_t)(k0 + d) * NS + gs] : 0.f;
                wtile[i] = wrd[(size_t)(k0 + d) * NT + x];
            }
            __syncthreads();
#pragma unroll 4
            for (int d = 0; d < 64; ++d) {
                float4 wv = *(const float4*)&wtile[d * 64 + t0];
                float4 cv = *(const float4*)&ctile[d * 64 + s0l];
                fma4x4(acc, cv, wv);
            }
        }
#pragma unroll
        for (int ii = 0; ii < 4; ++ii) {
            int s = sbase + s0l + ii;
            if (s < NS) {
                scoresB[s * 64 + t0 + 0] = acc[ii][0];
                scoresB[s * 64 + t0 + 1] = acc[ii][1];
                scoresB[s * 64 + t0 + 2] = acc[ii][2];
                scoresB[s * 64 + t0 + 3] = acc[ii][3];
            }
        }
    }
    __syncthreads();

    // ---------- Phase 2: masked softmax over t per row s; store exp(T1*a1) ----------
    int lane = tid & 31, warp = tid >> 5;
    int cap = cap_lens[c];
    for (int s = warp; s < NS; s += 8) {
        float v0 = scoresB[s * 64 + lane];
        float v1 = scoresB[s * 64 + 32 + lane];
        float m0 = (lane < cap) ? v0 : -INFINITY;
        float m1 = (lane + 32 < cap) ? v1 : -INFINITY;
        float mx = fmaxf(m0, m1);
#pragma unroll
        for (int o = 16; o; o >>= 1) mx = fmaxf(mx, __shfl_xor_sync(0xffffffffu, mx, o));
        float e0 = (lane < cap) ? expf(v0 - mx) : 0.f;
        float e1 = (lane + 32 < cap) ? expf(v1 - mx) : 0.f;
        float sm = e0 + e1;
#pragma unroll
        for (int o = 16; o; o >>= 1) sm += __shfl_xor_sync(0xffffffffu, sm, o);
        float inv = 1.f / sm;
        a2buf[s * 64 + lane]      = expf(TEMP1 * (e0 * inv));
        a2buf[s * 64 + 32 + lane] = expf(TEMP1 * (e1 * inv));
    }
    if (tid < (SP - NS) * 64) a2buf[NS * 64 + tid] = 0.f;   // zero pad rows
    __syncthreads();

    // ---------- Phase 3+4: column sums (softmax over s) and w12 ----------
    {
        int t = tid & 63, q = tid >> 6;
        float ps = 0.f, pw = 0.f;
        for (int s = q; s < NS; s += 4) {
            float av = a2buf[s * 64 + t];
            ps += av;
            pw = fmaf(av, scoresB[s * 64 + t], pw);
        }
        red[q * 64 + t] = ps;
        __syncthreads();
        if (tid < 64)
            colinv[tid] = 1.f / (red[tid] + red[64 + tid] + red[128 + tid] + red[192 + tid]);
        __syncthreads();
        red[q * 64 + t] = pw;
        __syncthreads();
        if (tid < 64) {
            float wt = red[tid] + red[64 + tid] + red[128 + tid] + red[192 + tid];
            w12s[tid] = wt * colinv[tid];
            w2sq[tid] = 0.f;
        }
        __syncthreads();
        for (int i = tid; i < NS * 64; i += 256) a2buf[i] *= colinv[i & 63];
    }
    __syncthreads();

    // ---------- Phase 5: w2sq[t] = a2_t^T G_b a2_t (Gram quadratic form) ----------
    {
        float* Gsub = scoresB;  // scores dead, reuse
        const float* Gb = g_G + (size_t)b * NS * NS;
        for (int ch = 0; ch < 6; ++ch) {
            int sp0 = ch * 64;
            __syncthreads();
            for (int i = tid; i < SP * 64; i += 256) {
                int k = i >> 6, j = i & 63;
                int sj = sp0 + j;
                Gsub[i] = (k < NS && sj < NS) ? Gb[(size_t)k * NS + sj] : 0.f;
            }
            __syncthreads();
            float acc[4][4] = {};
#pragma unroll 4
            for (int k = 0; k < SP; ++k) {
                float4 av = *(const float4*)&a2buf[k * 64 + t0];
                float4 gv = *(const float4*)&Gsub[k * 64 + s0l];
                fma4x4(acc, gv, av);  // acc[ii][jj] = Y[sp0+s0l+ii][t0+jj]
            }
            float con[4] = {0.f, 0.f, 0.f, 0.f};
#pragma unroll
            for (int ii = 0; ii < 4; ++ii) {
                int sp = sp0 + s0l + ii;
                if (sp < NS) {
                    float4 av = *(const float4*)&a2buf[sp * 64 + t0];
                    con[0] = fmaf(av.x, acc[ii][0], con[0]);
                    con[1] = fmaf(av.y, acc[ii][1], con[1]);
                    con[2] = fmaf(av.z, acc[ii][2], con[2]);
                    con[3] = fmaf(av.w, acc[ii][3], con[3]);
                }
            }
            atomicAdd(&w2sq[t0 + 0], con[0]);
            atomicAdd(&w2sq[t0 + 1], con[1]);
            atomicAdd(&w2sq[t0 + 2], con[2]);
            atomicAdd(&w2sq[t0 + 3], con[3]);
        }
    }
    __syncthreads();

    // ---------- Phase 6: similarity row ----------
    if (tid < 64) {
        int t = tid;
        float w2 = sqrtf(w2sq[t]);
        float w1 = g_w1n[c * NT + t];
        float sim = w12s[t] / fmaxf(w1 * w2, EPSV);
        red[t] = (t < cap) ? expf(TEMP2 * sim) : 0.f;
    }
    __syncthreads();
    if (tid == 0) {
        float sum = 0.f;
        for (int t = 0; t < NT; ++t) sum += red[t];
        g_sims[b * NB + c] = TEMP3 * logf(sum);   // similarities[img][cap]
    }

    // ---------- Phase 7: att_maps for diagonal pairs ----------
    if (write_att && b == c) {
        float* ao = att_out + (size_t)b * NT * NS;
        for (int i = tid; i < NS * NT; i += 256) {
            int s = i >> 6, t = i & 63;
            ao[(size_t)t * NS + s] = a2buf[i];
        }
    }
}

// ============================================================
// Final loss: 4 diagonal cross-entropies; 1 block, 64 threads
// ============================================================
__global__ void loss_kernel(float* __restrict__ out) {
    __shared__ float part[4][NB];
    int i = threadIdx.x;
    if (i < NB) {
        const float* Ms = g_sims;
        const float* Mg = g_sc0;
        float m, sum;
        // sims rows
        m = -INFINITY;
        for (int j = 0; j < NB; ++j) m = fmaxf(m, Ms[i * NB + j]);
        sum = 0.f;
        for (int j = 0; j < NB; ++j) sum += expf(Ms[i * NB + j] - m);
        part[0][i] = m + logf(sum) - Ms[i * NB + i];
        // sims cols
        m = -INFINITY;
        for (int j = 0; j < NB; ++j) m = fmaxf(m, Ms[j * NB + i]);
        sum = 0.f;
        for (int j = 0; j < NB; ++j) sum += expf(Ms[j * NB + i] - m);
        part[1][i] = m + logf(sum) - Ms[i * NB + i];
        // global rows
        m = -INFINITY;
        for (int j = 0; j < NB; ++j) m = fmaxf(m, Mg[i * NB + j]);
        sum = 0.f;
        for (int j = 0; j < NB; ++j) sum += expf(Mg[i * NB + j] - m);
        part[2][i] = m + logf(sum) - Mg[i * NB + i];
        // global cols
        m = -INFINITY;
        for (int j = 0; j < NB; ++j) m = fmaxf(m, Mg[j * NB + i]);
        sum = 0.f;
        for (int j = 0; j < NB; ++j) sum += expf(Mg[j * NB + i] - m);
        part[3][i] = m + logf(sum) - Mg[i * NB + i];
    }
    __syncthreads();
    if (i == 0) {
        float l = 0.f;
        for (int k = 0; k < 4; ++k) {
            float s = 0.f;
            for (int j = 0; j < NB; ++j) s += part[k][j];
            l += s * (1.f / (float)NB);
        }
        out[0] = l;
    }
}

// ============================================================
extern "C" void kernel_launch(void* const* d_in, const int* in_sizes, int n_in,
                              void* d_out, int out_size) {
    const float* gfeat  = (const float*)d_in[0];  // [48,768]
    const float* localf = (const float*)d_in[1];  // [48,768,19,19]
    const float* words  = (const float*)d_in[2];  // [48,768,64]
    const float* sfeat  = (const float*)d_in[3];  // [48,768]
    const int*   caps   = (const int*)d_in[4];    // [48]
    float* out = (float*)d_out;

    cudaFuncSetAttribute(pair_kernel, cudaFuncAttributeMaxDynamicSharedMemorySize, SMEM_BYTES);

    gram_kernel<<<dim3(6, 6, NB), 256>>>(localf);
    norms_kernel<<<NB, 64>>>(words, gfeat, sfeat);
    gscore_kernel<<<NB, 256>>>(gfeat, sfeat);

    int wa = (out_size >= 1 + NB * NT * NS) ? 1 : 0;
    pair_kernel<<<NB * NB, 256, SMEM_BYTES>>>(localf, words, caps, out + 1, wa);
    loss_kernel<<<1, 64>>>(out);
}

// round 2
// speedup vs baseline: 2.0911x; 2.0911x over previous
#include <cuda_runtime.h>
#include <math.h>
#include <stdint.h>

#define NB 48
#define NC 768
#define NS 361
#define NT 64
#define SPAD 384

#define TEMP1 4.0f
#define TEMP2 5.0f
#define TEMP3 10.0f
#define EPSV  1e-8f

// ----- device scratch (no allocations allowed) -----
__device__ float g_ctxp[(size_t)NB * NC * SPAD];   // padded ctx [b][d][384]
__device__ float g_G[(size_t)NB * SPAD * SPAD];    // padded Gram [b][384][384]
__device__ float g_w1n[NB * NT];
__device__ float g_gn[NB];
__device__ float g_sn[NB];
__device__ float g_sc0[NB * NB];
__device__ float g_sims[NB * NB];                  // similarities[img][cap]

__device__ __forceinline__ void fma8x8(float (&acc)[8][8],
                                       const float4 a0, const float4 a1,
                                       const float4 b0, const float4 b1) {
    float av[8] = {a0.x, a0.y, a0.z, a0.w, a1.x, a1.y, a1.z, a1.w};
    float bv[8] = {b0.x, b0.y, b0.z, b0.w, b1.x, b1.y, b1.z, b1.w};
#pragma unroll
    for (int i = 0; i < 8; ++i)
#pragma unroll
        for (int j = 0; j < 8; ++j)
            acc[i][j] = fmaf(av[i], bv[j], acc[i][j]);
}

// ============================================================
// Pad ctx into [b][d][384] with zero pad cols
// ============================================================
__global__ void pad_kernel(const float* __restrict__ lf) {
    size_t i = (size_t)blockIdx.x * blockDim.x + threadIdx.x;
    if (i < (size_t)NB * NC * SPAD) {
        int x = (int)(i % SPAD);
        size_t r = i / SPAD;
        g_ctxp[i] = (x < NS) ? lf[r * NS + x] : 0.f;
    }
}

// ============================================================
// Gram: G_b = ctx_b^T ctx_b, padded 384x384, symmetric blocks
// grid (6, NB), 256 threads; 128x128 tile per block, 8x8/thread
// ============================================================
__global__ __launch_bounds__(256) void gram_kernel() {
    const int byA[6] = {0, 0, 0, 1, 1, 2};
    const int bxA[6] = {0, 1, 2, 1, 2, 2};
    int p = blockIdx.x, b = blockIdx.y;
    int i0 = byA[p] * 128, j0 = bxA[p] * 128;
    __shared__ float At[32 * 128];
    __shared__ float Bt[32 * 128];
    const float* cp = g_ctxp + (size_t)b * NC * SPAD;
    int tid = threadIdx.x;
    int ti = tid & 15, si = tid >> 4;
    int il = si * 8, jl = ti * 8;
    float acc[8][8] = {};
    for (int kc = 0; kc < 24; ++kc) {
        int k0 = kc * 32;
        __syncthreads();
        for (int i4 = tid; i4 < 1024; i4 += 256) {
            int kk = i4 >> 5, x4 = i4 & 31;
            const float* base = cp + (size_t)(k0 + kk) * SPAD;
            ((float4*)At)[i4] = *(const float4*)(base + i0 + x4 * 4);
            ((float4*)Bt)[i4] = *(const float4*)(base + j0 + x4 * 4);
        }
        __syncthreads();
#pragma unroll 4
        for (int k = 0; k < 32; ++k) {
            float4 a0 = *(const float4*)&At[k * 128 + il];
            float4 a1 = *(const float4*)&At[k * 128 + il + 4];
            float4 b0 = *(const float4*)&Bt[k * 128 + jl];
            float4 b1 = *(const float4*)&Bt[k * 128 + jl + 4];
            fma8x8(acc, a0, a1, b0, b1);
        }
    }
    float* Gb = g_G + (size_t)b * SPAD * SPAD;
#pragma unroll
    for (int ii = 0; ii < 8; ++ii) {
        int row = i0 + il + ii;
        *(float4*)&Gb[(size_t)row * SPAD + j0 + jl] =
            make_float4(acc[ii][0], acc[ii][1], acc[ii][2], acc[ii][3]);
        *(float4*)&Gb[(size_t)row * SPAD + j0 + jl + 4] =
            make_float4(acc[ii][4], acc[ii][5], acc[ii][6], acc[ii][7]);
    }
    if (i0 != j0) {
#pragma unroll
        for (int jj = 0; jj < 8; ++jj) {
            int row = j0 + jl + jj;
#pragma unroll
            for (int ii = 0; ii < 8; ++ii)
                Gb[(size_t)row * SPAD + i0 + il + ii] = acc[ii][jj];
        }
    }
}

// ============================================================
// Norms
// ============================================================
__global__ void norms_kernel(const float* __restrict__ words,
                             const float* __restrict__ gfeat,
                             const float* __restrict__ sfeat) {
    int c = blockIdx.x;
    int tid = threadIdx.x;
    float s = 0.f;
    for (int d = 0; d < NC; ++d) {
        float v = words[((size_t)c * NC + d) * NT + tid];
        s = fmaf(v, v, s);
    }
    g_w1n[c * NT + tid] = sqrtf(s);

    float a = 0.f, bb = 0.f;
    for (int d = tid; d < NC; d += 64) {
        float v = gfeat[(size_t)c * NC + d];
        float w = sfeat[(size_t)c * NC + d];
        a = fmaf(v, v, a);
        bb = fmaf(w, w, bb);
    }
#pragma unroll
    for (int o = 16; o; o >>= 1) {
        a  += __shfl_xor_sync(0xffffffffu, a, o);
        bb += __shfl_xor_sync(0xffffffffu, bb, o);
    }
    __shared__ float r[4];
    int warp = tid >> 5, lane = tid & 31;
    if (lane == 0) { r[warp] = a; r[2 + warp] = bb; }
    __syncthreads();
    if (tid == 0) {
        g_gn[c] = sqrtf(r[0] + r[1]);
        g_sn[c] = sqrtf(r[2] + r[3]);
    }
}

// ============================================================
// Global scores0
// ============================================================
__global__ void gscore_kernel(const float* __restrict__ gfeat,
                              const float* __restrict__ sfeat) {
    int i = blockIdx.x;
    int tid = threadIdx.x;
    int warp = tid >> 5, lane = tid & 31;
    for (int j = warp; j < NB; j += 8) {
        float acc = 0.f;
        for (int d = lane; d < NC; d += 32)
            acc = fmaf(gfeat[(size_t)i * NC + d], sfeat[(size_t)j * NC + d], acc);
#pragma unroll
        for (int o = 16; o; o >>= 1) acc += __shfl_xor_sync(0xffffffffu, acc, o);
        if (lane == 0) {
            float denom = fmaxf(g_gn[i] * g_sn[j], EPSV);
            g_sc0[i * NB + j] = TEMP3 * acc / denom;
        }
    }
}

// ============================================================
// Per-pair kernel: one CTA per (cap c, img b); 384 threads.
// smem: buf[384*64] | ctile[32*384] | wtile[32*64] | red[3072] |
//       red2[768] | colinv[64] | w12s[64]
// ============================================================
#define SMEM_FLOATS (SPAD * NT + 32 * SPAD + 32 * NT + 3072 + 768 + 64 + 64)
#define SMEM_BYTES  (SMEM_FLOATS * 4)

__global__ __launch_bounds__(384, 1) void pair_kernel(
    const float* __restrict__ words,     // [B,C,T]
    const int*   __restrict__ cap_lens,
    float*       __restrict__ att_out,
    int write_att) {
    extern __shared__ float smem[];
    float* buf    = smem;                         // 24576 (scores -> a2u)
    float* ctile  = buf + SPAD * NT;              // 12288
    float* wtile  = ctile + 32 * SPAD;            // 2048
    float* red    = wtile + 32 * NT;              // 3072
    float* red2   = red + 3072;                   // 768
    float* colinv = red2 + 768;                   // 64
    float* w12s   = colinv + 64;                  // 64

    int tid = threadIdx.x;
    int bidx = blockIdx.x;
    int b = bidx % NB;        // image
    int c = bidx / NB;        // caption
    const float* cpx = g_ctxp + (size_t)b * NC * SPAD;
    const float* wrd = words + (size_t)c * NC * NT;

    int sg = tid >> 3;            // 0..47
    int tg = tid & 7;             // 0..7
    int s0l = sg * 8, t0 = tg * 8;

    // ---------- Phase 1: scores[s][t] over all 384 rows, 8x8/thread ----------
    {
        float acc[8][8] = {};
        for (int kc = 0; kc < 24; ++kc) {
            int k0 = kc * 32;
            __syncthreads();
            for (int i4 = tid; i4 < 3072; i4 += 384) {
                int kk = i4 / 96;
                int x4 = i4 - kk * 96;
                ((float4*)ctile)[i4] =
                    *(const float4*)(cpx + (size_t)(k0 + kk) * SPAD + x4 * 4);
            }
            for (int i4 = tid; i4 < 512; i4 += 384) {
                int kk = i4 >> 4, x4 = i4 & 15;
                ((float4*)wtile)[i4] =
                    *(const float4*)(wrd + (size_t)(k0 + kk) * NT + x4 * 4);
            }
            __syncthreads();
#pragma unroll 4
            for (int k = 0; k < 32; ++k) {
                float4 a0 = *(const float4*)&ctile[k * SPAD + s0l];
                float4 a1 = *(const float4*)&ctile[k * SPAD + s0l + 4];
                float4 b0 = *(const float4*)&wtile[k * NT + t0];
                float4 b1 = *(const float4*)&wtile[k * NT + t0 + 4];
                fma8x8(acc, a0, a1, b0, b1);
            }
        }
#pragma unroll
        for (int ii = 0; ii < 8; ++ii) {
            *(float4*)&buf[(s0l + ii) * NT + t0] =
                make_float4(acc[ii][0], acc[ii][1], acc[ii][2], acc[ii][3]);
            *(float4*)&buf[(s0l + ii) * NT + t0 + 4] =
                make_float4(acc[ii][4], acc[ii][5], acc[ii][6], acc[ii][7]);
        }
    }
    __syncthreads();

    // ---------- Phase 2: row softmax over t -> a2u; accumulate colsum & w12 ----------
    int warp = tid >> 5, lane = tid & 31;
    int cap = cap_lens[c];
    {
        float ps0 = 0.f, ps1 = 0.f, pw0 = 0.f, pw1 = 0.f;
        for (int s = warp; s < NS; s += 12) {
            float v0 = buf[s * 64 + lane];
            float v1 = buf[s * 64 + 32 + lane];
            float m0 = (lane < cap) ? v0 : -1e30f;
            float m1 = (lane + 32 < cap) ? v1 : -1e30f;
            float mx = fmaxf(m0, m1);
#pragma unroll
            for (int o = 16; o; o >>= 1)
                mx = fmaxf(mx, __shfl_xor_sync(0xffffffffu, mx, o));
            float e0 = (lane < cap) ? __expf(v0 - mx) : 0.f;
            float e1 = (lane + 32 < cap) ? __expf(v1 - mx) : 0.f;
            float sm = e0 + e1;
#pragma unroll
            for (int o = 16; o; o >>= 1)
                sm += __shfl_xor_sync(0xffffffffu, sm, o);
            float inv = 1.f / sm;
            float u0 = __expf(TEMP1 * (e0 * inv));
            float u1 = __expf(TEMP1 * (e1 * inv));
            buf[s * 64 + lane] = u0;
            buf[s * 64 + 32 + lane] = u1;
            ps0 += u0; ps1 += u1;
            pw0 = fmaf(u0, v0, pw0);
            pw1 = fmaf(u1, v1, pw1);
        }
        red[warp * 64 + lane] = ps0;
        red[warp * 64 + 32 + lane] = ps1;
        red2[warp * 64 + lane] = pw0;
        red2[warp * 64 + 32 + lane] = pw1;
        // zero pad rows 361..383
        for (int i = tid; i < (SPAD - NS) * NT; i += 384)
            buf[NS * NT + i] = 0.f;
    }
    __syncthreads();
    if (tid < 64) {
        float cs = 0.f, wsum = 0.f;
#pragma unroll
        for (int w = 0; w < 12; ++w) {
            cs += red[w * 64 + tid];
            wsum += red2[w * 64 + tid];
        }
        float ci = 1.f / cs;
        colinv[tid] = ci;
        w12s[tid] = wsum * ci;
    }

    // ---------- Phase 5: w2raw[t] = a2u^T G_b a2u, 8x8/thread GEMM + contraction ----
    float wacc[8] = {};
    {
        float acc[8][8] = {};
        const float* Gb = g_G + (size_t)b * SPAD * SPAD;
        for (int kc = 0; kc < 12; ++kc) {
            int k0 = kc * 32;
            __syncthreads();
            for (int i4 = tid; i4 < 3072; i4 += 384) {
                int kk = i4 / 96;
                int x4 = i4 - kk * 96;
                ((float4*)ctile)[i4] =
                    *(const float4*)(Gb + (size_t)(k0 + kk) * SPAD + x4 * 4);
            }
            __syncthreads();
#pragma unroll 4
            for (int k = 0; k < 32; ++k) {
                float4 a0 = *(const float4*)&ctile[k * SPAD + s0l];
                float4 a1 = *(const float4*)&ctile[k * SPAD + s0l + 4];
                float4 b0 = *(const float4*)&buf[(k0 + k) * NT + t0];
                float4 b1 = *(const float4*)&buf[(k0 + k) * NT + t0 + 4];
                fma8x8(acc, a0, a1, b0, b1);
            }
        }
#pragma unroll
        for (int ii = 0; ii < 8; ++ii) {
            float4 av0 = *(const float4*)&buf[(s0l + ii) * NT + t0];
            float4 av1 = *(const float4*)&buf[(s0l + ii) * NT + t0 + 4];
            wacc[0] = fmaf(av0.x, acc[ii][0], wacc[0]);
            wacc[1] = fmaf(av0.y, acc[ii][1], wacc[1]);
            wacc[2] = fmaf(av0.z, acc[ii][2], wacc[2]);
            wacc[3] = fmaf(av0.w, acc[ii][3], wacc[3]);
            wacc[4] = fmaf(av1.x, acc[ii][4], wacc[4]);
            wacc[5] = fmaf(av1.y, acc[ii][5], wacc[5]);
            wacc[6] = fmaf(av1.z, acc[ii][6], wacc[6]);
            wacc[7] = fmaf(av1.w, acc[ii][7], wacc[7]);
        }
    }
    __syncthreads();
    *(float4*)&red[sg * 64 + t0] = make_float4(wacc[0], wacc[1], wacc[2], wacc[3]);
    *(float4*)&red[sg * 64 + t0 + 4] = make_float4(wacc[4], wacc[5], wacc[6], wacc[7]);
    __syncthreads();

    // ---------- Phase 6: similarity row ----------
    if (tid < 64) {
        float w2r = 0.f;
#pragma unroll
        for (int g = 0; g < 48; ++g) w2r += red[g * 64 + tid];
        float w2 = colinv[tid] * sqrtf(w2r);
        float w1 = g_w1n[c * NT + tid];
        float sim = w12s[tid] / fmaxf(w1 * w2, EPSV);
        red2[tid] = (tid < cap) ? __expf(TEMP2 * sim) : 0.f;
    }
    __syncthreads();
    if (tid == 0) {
        float sum = 0.f;
        for (int t = 0; t < NT; ++t) sum += red2[t];
        g_sims[b * NB + c] = TEMP3 * logf(sum);
    }

    // ---------- Phase 7: att_maps for diagonal pairs ----------
    if (write_att && b == c) {
        float* ao = att_out + (size_t)b * NT * NS;
        for (int i = tid; i < NS * NT; i += 384) {
            int s = i >> 6, t = i & 63;
            ao[(size_t)t * NS + s] = buf[i] * colinv[t];
        }
    }
}

// ============================================================
// Final loss
// ============================================================
__global__ void loss_kernel(float* __restrict__ out) {
    __shared__ float part[4][NB];
    int i = threadIdx.x;
    if (i < NB) {
        const float* Ms = g_sims;
        const float* Mg = g_sc0;
        float m, sum;
        m = -INFINITY;
        for (int j = 0; j < NB; ++j) m = fmaxf(m, Ms[i * NB + j]);
        sum = 0.f;
        for (int j = 0; j < NB; ++j) sum += expf(Ms[i * NB + j] - m);
        part[0][i] = m + logf(sum) - Ms[i * NB + i];
        m = -INFINITY;
        for (int j = 0; j < NB; ++j) m = fmaxf(m, Ms[j * NB + i]);
        sum = 0.f;
        for (int j = 0; j < NB; ++j) sum += expf(Ms[j * NB + i] - m);
        part[1][i] = m + logf(sum) - Ms[i * NB + i];
        m = -INFINITY;
        for (int j = 0; j < NB; ++j) m = fmaxf(m, Mg[i * NB + j]);
        sum = 0.f;
        for (int j = 0; j < NB; ++j) sum += expf(Mg[i * NB + j] - m);
        part[2][i] = m + logf(sum) - Mg[i * NB + i];
        m = -INFINITY;
        for (int j = 0; j < NB; ++j) m = fmaxf(m, Mg[j * NB + i]);
        sum = 0.f;
        for (int j = 0; j < NB; ++j) sum += expf(Mg[j * NB + i] - m);
        part[3][i] = m + logf(sum) - Mg[i * NB + i];
    }
    __syncthreads();
    if (i == 0) {
        float l = 0.f;
        for (int k = 0; k < 4; ++k) {
            float s = 0.f;
            for (int j = 0; j < NB; ++j) s += part[k][j];
            l += s * (1.f / (float)NB);
        }
        out[0] = l;
    }
}

// ============================================================
extern "C" void kernel_launch(void* const* d_in, const int* in_sizes, int n_in,
                              void* d_out, int out_size) {
    const float* gfeat  = (const float*)d_in[0];  // [48,768]
    const float* localf = (const float*)d_in[1];  // [48,768,19,19]
    const float* words  = (const float*)d_in[2];  // [48,768,64]
    const float* sfeat  = (const float*)d_in[3];  // [48,768]
    const int*   caps   = (const int*)d_in[4];    // [48]
    float* out = (float*)d_out;

    cudaFuncSetAttribute(pair_kernel, cudaFuncAttributeMaxDynamicSharedMemorySize, SMEM_BYTES);

    size_t tot = (size_t)NB * NC * SPAD;
    pad_kernel<<<(unsigned)((tot + 255) / 256), 256>>>(localf);
    gram_kernel<<<dim3(6, NB), 256>>>();
    norms_kernel<<<NB, 64>>>(words, gfeat, sfeat);
    gscore_kernel<<<NB, 256>>>(gfeat, sfeat);

    int wa = (out_size >= 1 + NB * NT * NS) ? 1 : 0;
    pair_kernel<<<NB * NB, 384, SMEM_BYTES>>>(words, caps, out + 1, wa);
    loss_kernel<<<1, 64>>>(out);
}